// round 9
// baseline (speedup 1.0000x reference)
#include <cuda_runtime.h>
#include <cstddef>

#define LSEQ 256
#define NB   8
#define NC   64
#define TRI  32640    // packed triangle, diagonal-major
#define DPAD 64

// t = max_c scores, diagonal-packed: g_td[b*TRI + off1(w) + i]
__device__ float g_td[NB * TRI];

// off1(w) = (w-1)*256 - (w-1)w/2 ; diag w holds cells i = 0..255-w
__host__ __device__ __forceinline__ int off1_of(int w) {
    return (w - 1) * 256 - (((w - 1) * w) >> 1);
}

// ---------------------------------------------------------------------------
// Kernel 1: t[b,i,e] = max over C of scores[b,i,e,:], upper triangle only.
// ---------------------------------------------------------------------------
__global__ void max_kernel(const float* __restrict__ scores) {
    const int i    = blockIdx.x;          // 0 .. 254
    const int b    = blockIdx.y;
    const int warp = threadIdx.x >> 5;
    const int lane = threadIdx.x & 31;

    for (int e = i + 1 + warp; e < LSEQ; e += 8) {
        const float* p = scores + (((size_t)b * LSEQ + i) * LSEQ + e) * NC;
        float v = fmaxf(p[lane], p[lane + 32]);
        #pragma unroll
        for (int o = 16; o > 0; o >>= 1)
            v = fmaxf(v, __shfl_xor_sync(0xffffffffu, v, o));
        if (lane == 0)
            g_td[b * TRI + off1_of(e - i) + i] = v;
    }
}

// ---------------------------------------------------------------------------
// Kernel 2: CKY inside (max semiring), one 1024-thread CTA per batch.
// Diagonal-packed chart in SMEM: lane-stride 1 on every operand ->
// conflict-free LDS. Per pass: 4 widths (w..w+3).
//  Bulk (adaptive j-split): j in [4, w-1] valid for all 4 widths. One shared
//   left load L = D[off1(j)+c]; four right loads on diagonals w+d-j, pointers
//   ra_d stepped by (st+d) per j.
//  Pre-combine: 1024 threads reduce G group-partials -> VV[d][cell].
//  Serial tail (tid<256, partial barriers): boundary j in {1,2,3} and
//   [max(w,4), wd-1] (fresh diagonals), + t, store.
// ---------------------------------------------------------------------------
__global__ __launch_bounds__(1024, 1)
void dp_kernel(const int* __restrict__ lens, float* __restrict__ out) {
    const int b = blockIdx.x;
    extern __shared__ float S[];
    float* D  = S;                          // TRI + DPAD chart
    float* P0 = S + TRI + DPAD;             // 4 x 1024 bulk partials
    float* VV = P0 + 4 * 1024;              // 4 x 256 pre-combined
    int*   At = (int*)(VV + 4 * 256);       // off1(w), w in [1,255]
    const float* tb  = g_td + b * TRI;
    const int    tid = threadIdx.x;

    if (tid >= 1 && tid < 256) At[tid] = off1_of(tid);
    if (tid == 0) At[0] = 0;
    for (int q = tid; q < DPAD; q += 1024) D[TRI + q] = -1e30f;
    if (tid < 255) D[tid] = tb[tid];        // width-1 diagonal
    __syncthreads();

    // Serial-thread state: prefetched t for widths 2..5 (clamped per width).
    float t0 = 0.f, t1 = 0.f, t2 = 0.f, t3 = 0.f;
    if (tid < 256) {
        #pragma unroll
        for (int q = 0; q < 4; ++q) {
            int wn = 2 + q;
            int cl = tid < 255 - wn ? tid : 255 - wn;
            float tv = tb[At[wn] + cl];
            if (q == 0) t0 = tv; else if (q == 1) t1 = tv;
            else if (q == 2) t2 = tv; else t3 = tv;
        }
    }
    __syncthreads();

    for (int w = 2; w < LSEQ; w += 4) {
        const int n = LSEQ - w;              // cells at base width w
        const int s = (n > 128) ? 8 : (n > 64 ? 7 : 6);
        const int c = tid & ((1 << s) - 1);
        const int g = tid >> s;

        // ---- bulk: j in [4, w-1] for all four widths
        float a0 = -1e30f, a1 = -1e30f, a2 = -1e30f, a3 = -1e30f;
        if (c < n && w > 4) {
            const int m   = w - 4;
            const int jlo = 4 + ((g * m) >> (10 - s));
            const int jhi = 4 + (((g + 1) * m) >> (10 - s));
            if (jlo < jhi) {
                int la  = At[jlo] + c;           // left: D[off1(j)+c]
                int lst = 256 - jlo;             // la step (decrements)
                const int v0 = w - jlo;          // right diag, d=0
                int ra0 = At[v0]     + c + jlo;  // right: D[off1(w+d-j)+c+j]
                int ra1 = At[v0 + 1] + c + jlo;
                int ra2 = At[v0 + 2] + c + jlo;
                int ra3 = At[v0 + 3] + c + jlo;
                int st  = v0 - 256;              // ra0 step; ra_d: st + d
                #pragma unroll 4
                for (int j = jlo; j < jhi; ++j) {
                    const float L = D[la];
                    a0 = fmaxf(a0, L + D[ra0]);
                    a1 = fmaxf(a1, L + D[ra1]);
                    a2 = fmaxf(a2, L + D[ra2]);
                    a3 = fmaxf(a3, L + D[ra3]);
                    la  += lst; --lst;
                    ra0 += st;
                    ra1 += st + 1;
                    ra2 += st + 2;
                    ra3 += st + 3;
                    --st;
                }
            }
        }
        P0[tid]        = a0;
        P0[1024 + tid] = a1;
        P0[2048 + tid] = a2;
        P0[3072 + tid] = a3;
        __syncthreads();

        // ---- pre-combine: reduce G group-partials per (width d, cell cc)
        {
            const int d  = tid >> 8;
            const int cc = tid & 255;
            const int G  = 1024 >> s;
            const float* PP = P0 + (d << 10);
            float v = -1e30f;
            if (cc < n) {
                #pragma unroll 4
                for (int k = 0; k < G; ++k)
                    v = fmaxf(v, PP[(k << s) + cc]);
            }
            VV[(d << 8) + cc] = v;
        }
        __syncthreads();

        // ---- serial tail: boundary terms + store, width by width
        if (tid < 256) {
            #pragma unroll
            for (int d = 0; d < 4; ++d) {
                const int wd = w + d;
                if (wd <= 255 && tid < LSEQ - wd) {
                    float v = VV[(d << 8) + tid];
                    // j = 1,2,3 (old diagonals)
                    v = fmaxf(v, D[tid] + D[At[wd - 1] + tid + 1]);
                    if (wd >= 3)
                        v = fmaxf(v, D[At[2] + tid] + D[At[wd - 2] + tid + 2]);
                    if (wd >= 4)
                        v = fmaxf(v, D[At[3] + tid] + D[At[wd - 3] + tid + 3]);
                    // high fixups: j in [max(w,4), wd-1] (left diag fresh)
                    for (int j = (w > 4 ? w : 4); j < wd; ++j)
                        v = fmaxf(v, D[At[j] + tid] + D[At[wd - j] + tid + j]);
                    const float tt = (d == 0) ? t0 : (d == 1) ? t1
                                   : (d == 2) ? t2 : t3;
                    D[At[wd] + tid] = v + tt;
                }
                asm volatile("bar.sync 1, 256;" ::: "memory");
            }
            // prefetch t for next pass (widths w+4..w+7), clamped
            #pragma unroll
            for (int q = 0; q < 4; ++q) {
                int wn = w + 4 + q; if (wn > 255) wn = 255;
                int cl = tid < 255 - wn ? tid : 255 - wn;
                float tv = tb[At[wn] + cl];
                if (q == 0) t0 = tv; else if (q == 1) t1 = tv;
                else if (q == 2) t2 = tv; else t3 = tv;
            }
        }
        __syncthreads();
    }

    if (tid == 0) {
        int len = lens[b];
        len = len < 1 ? 1 : (len > 255 ? 255 : len);
        out[b] = D[At[len]];                 // s[0, len]
    }
}

// ---------------------------------------------------------------------------
extern "C" void kernel_launch(void* const* d_in, const int* in_sizes, int n_in,
                              void* d_out, int out_size) {
    const float* scores = (const float*)d_in[0];
    const int*   lens   = (const int*)d_in[1];
    float*       out    = (float*)d_out;
    (void)in_sizes; (void)n_in; (void)out_size;

    const int smem = (TRI + DPAD + 4 * 1024 + 4 * 256 + 256) * (int)sizeof(float);
    cudaFuncSetAttribute(dp_kernel,
                         cudaFuncAttributeMaxDynamicSharedMemorySize, smem);

    max_kernel<<<dim3(LSEQ - 1, NB), 256>>>(scores);
    dp_kernel<<<NB, 1024, smem>>>(lens, out);
}

// round 10
// speedup vs baseline: 1.1899x; 1.1899x over previous
#include <cuda_runtime.h>
#include <cstddef>

#define LSEQ 256
#define NB   8
#define NC   64
#define PTOT 40960   // padded row-layout size (32640 + per-row pads < 40576)
#define DPAD 512     // slack for discarded-lane bulk reads

// Bank-aligned row starts: g_rs[i] = start of row i, with g_rs[i] % 32 == i % 32
__device__ int g_rs[257];

// t = max_c scores, padded-row layout: g_td[b*PTOT + g_rs[i] + (e-i-1)]
__device__ float g_td[NB * PTOT];

// ---------------------------------------------------------------------------
// Kernel 0: compute padded row-start table (row i has 255-i cells; pad so the
// next row starts at ≡ (i+1) mod 32). Runs once, trivial cost.
// ---------------------------------------------------------------------------
__global__ void rs_init_kernel() {
    if (threadIdx.x == 0) {
        int acc = 0;
        for (int i = 0; i < 256; ++i) {
            g_rs[i] = acc;
            int nxt = acc + (255 - i);
            nxt += (i + 1 - nxt) & 31;      // pad to ≡ i+1 (mod 32)
            acc = nxt;
        }
        g_rs[256] = acc;
    }
}

// ---------------------------------------------------------------------------
// Kernel 1: t[b,i,e] = max over C of scores[b,i,e,:], upper triangle only.
// ---------------------------------------------------------------------------
__global__ void max_kernel(const float* __restrict__ scores) {
    const int i    = blockIdx.x;          // 0 .. 254
    const int b    = blockIdx.y;
    const int warp = threadIdx.x >> 5;
    const int lane = threadIdx.x & 31;
    const int base = b * PTOT + g_rs[i] - i - 1;

    for (int e = i + 1 + warp; e < LSEQ; e += 8) {
        const float* p = scores + (((size_t)b * LSEQ + i) * LSEQ + e) * NC;
        float v = fmaxf(p[lane], p[lane + 32]);
        #pragma unroll
        for (int o = 16; o > 0; o >>= 1)
            v = fmaxf(v, __shfl_xor_sync(0xffffffffu, v, o));
        if (lane == 0)
            g_td[base + e] = v;
    }
}

// ---------------------------------------------------------------------------
// Kernel 2: CKY inside (max semiring), one 1024-thread CTA per batch.
// Padded-row chart in SMEM: every access pattern is a bank permutation
// (rs[i] ≡ i mod 32) -> zero conflicts, AND the four right operands per
// split point are adjacent (immediate offsets). Per pass: widths w..w+3.
//  Bulk (adaptive j-split): j in [4, w-1], valid for all 4 widths.
//  Pre-combine: 1024 threads reduce group partials -> VV[d][cell].
//  Serial tail (tid<256, partial barriers): boundary terms j in {1,2,3} and
//  [max(w,4), wd-1], + t, store.
// ---------------------------------------------------------------------------
__global__ __launch_bounds__(1024, 1)
void dp_kernel(const int* __restrict__ lens, float* __restrict__ out) {
    const int b = blockIdx.x;
    extern __shared__ float S[];
    float* D  = S;                          // PTOT + DPAD chart
    float* P0 = S + PTOT + DPAD;            // 4 x 1024 bulk partials
    float* VV = P0 + 4 * 1024;              // 4 x 256 pre-combined
    int*   rs = (int*)(VV + 4 * 256);       // padded row starts
    const float* tb  = g_td + b * PTOT;
    const int    tid = threadIdx.x;

    if (tid < 256) rs[tid] = g_rs[tid];
    __syncthreads();
    if (tid < 255) D[rs[tid]] = tb[rs[tid]];        // width-1 diagonal
    __syncthreads();

    // Serial-thread state: cached row starts + prefetched t for widths 2..5.
    int   rsc = 0, rs1 = 0, rs2 = 0, rs3 = 0, lim = 0;
    float t0 = 0.f, t1 = 0.f, t2 = 0.f, t3 = 0.f;
    if (tid < 256) {
        rsc = rs[tid];
        rs1 = rs[tid < 255 ? tid + 1 : 255];
        rs2 = rs[tid < 254 ? tid + 2 : 255];
        rs3 = rs[tid < 253 ? tid + 3 : 255];
        lim = rsc + (tid < 254 ? 254 - tid : 0);  // last valid col of row tid
        int i0 = rsc + 1;
        t0 = tb[i0     < lim ? i0     : lim];
        t1 = tb[i0 + 1 < lim ? i0 + 1 : lim];
        t2 = tb[i0 + 2 < lim ? i0 + 2 : lim];
        t3 = tb[i0 + 3 < lim ? i0 + 3 : lim];
    }
    __syncthreads();

    for (int w = 2; w < LSEQ; w += 4) {
        const int n = LSEQ - w;              // cells at base width w
        const int s = (n > 128) ? 8 : (n > 64 ? 7 : 6);
        const int c = tid & ((1 << s) - 1);
        const int g = tid >> s;

        // ---- bulk: j in [4, w-1] for all four widths
        float a0 = -1e30f, a1 = -1e30f, a2 = -1e30f, a3 = -1e30f;
        if (c < n && w > 4) {
            const int m   = w - 4;
            const int jlo = 4 + ((g * m) >> (10 - s));
            const int jhi = 4 + (((g + 1) * m) >> (10 - s));
            if (jlo < jhi) {
                const int lb = rs[c] - 1;        // left: D[lb + j]
                int tp = c + jlo;                // rs-table index
                int rb = w - jlo - 1;            // right col (base width)
                #pragma unroll 4
                for (int j = jlo; j < jhi; ++j) {
                    const float L  = D[lb + j];
                    const int   ra = rs[tp] + rb;
                    a0 = fmaxf(a0, L + D[ra]);
                    a1 = fmaxf(a1, L + D[ra + 1]);
                    a2 = fmaxf(a2, L + D[ra + 2]);
                    a3 = fmaxf(a3, L + D[ra + 3]);
                    ++tp; --rb;
                }
            }
        }
        P0[tid]        = a0;
        P0[1024 + tid] = a1;
        P0[2048 + tid] = a2;
        P0[3072 + tid] = a3;
        __syncthreads();

        // ---- pre-combine: reduce G group-partials per (width d, cell cc)
        {
            const int d  = tid >> 8;
            const int cc = tid & 255;
            const int G  = 1024 >> s;
            const float* PP = P0 + (d << 10);
            float v = -1e30f;
            if (cc < n) {
                #pragma unroll 4
                for (int k = 0; k < G; ++k)
                    v = fmaxf(v, PP[(k << s) + cc]);
            }
            VV[(d << 8) + cc] = v;
        }
        __syncthreads();

        // ---- serial tail: boundary terms + store, width by width
        if (tid < 256) {
            #pragma unroll
            for (int d = 0; d < 4; ++d) {
                const int wd = w + d;
                if (wd <= 255 && tid < LSEQ - wd) {
                    float v = VV[(d << 8) + tid];
                    v = fmaxf(v, D[rsc] + D[rs1 + wd - 2]);                 // j=1
                    if (wd >= 3) v = fmaxf(v, D[rsc + 1] + D[rs2 + wd - 3]); // j=2
                    if (wd >= 4) v = fmaxf(v, D[rsc + 2] + D[rs3 + wd - 4]); // j=3
                    for (int j = (w > 4 ? w : 4); j < wd; ++j)               // high
                        v = fmaxf(v, D[rsc + j - 1] + D[rs[tid + j] + wd - j - 1]);
                    const float tt = (d == 0) ? t0 : (d == 1) ? t1
                                   : (d == 2) ? t2 : t3;
                    D[rsc + wd - 1] = v + tt;
                }
                asm volatile("bar.sync 1, 256;" ::: "memory");
            }
            // prefetch t for next pass (widths w+4..w+7), clamped to row end
            int i0 = rsc + w + 3;
            t0 = tb[i0     < lim ? i0     : lim];
            t1 = tb[i0 + 1 < lim ? i0 + 1 : lim];
            t2 = tb[i0 + 2 < lim ? i0 + 2 : lim];
            t3 = tb[i0 + 3 < lim ? i0 + 3 : lim];
        }
        __syncthreads();
    }

    if (tid == 0) {
        int len = lens[b];
        len = len < 1 ? 1 : (len > 255 ? 255 : len);
        out[b] = D[len - 1];                 // s[0, len] = row 0, col len-1
    }
}

// ---------------------------------------------------------------------------
extern "C" void kernel_launch(void* const* d_in, const int* in_sizes, int n_in,
                              void* d_out, int out_size) {
    const float* scores = (const float*)d_in[0];
    const int*   lens   = (const int*)d_in[1];
    float*       out    = (float*)d_out;
    (void)in_sizes; (void)n_in; (void)out_size;

    const int smem = (PTOT + DPAD + 4 * 1024 + 4 * 256 + 256) * (int)sizeof(float);
    cudaFuncSetAttribute(dp_kernel,
                         cudaFuncAttributeMaxDynamicSharedMemorySize, smem);

    rs_init_kernel<<<1, 32>>>();
    max_kernel<<<dim3(LSEQ - 1, NB), 256>>>(scores);
    dp_kernel<<<NB, 1024, smem>>>(lens, out);
}